// round 17
// baseline (speedup 1.0000x reference)
#include <cuda_runtime.h>
#include <cuda_bf16.h>

#define NI 1024
#define NC 201
#define TT 100
// sigmoid(x) >= 0.3  <=>  x >= log(0.3/0.7)
#define THR (-0.8472978603872034f)

__device__ double g_acc;
__device__ unsigned int g_count;

__device__ __forceinline__ float softplus4(float4 v) {
    float sp;
    sp  = __logf(1.0f + __expf(v.x));
    sp += __logf(1.0f + __expf(v.y));
    sp += __logf(1.0f + __expf(v.z));
    sp += __logf(1.0f + __expf(v.w));
    return sp;
}

// One block per row i, 256 threads.
//  0: prefetch logits t=99 column (overlaps phase 1's DRAM stream)
//  1: labels[t] = argmax_c labels_[i,c,t]   (float4 loads, 8 c-chunks x 25 t-groups)
//  2: weight mask from last snippet: flag array + compacted class list
//  3: label-hit subtraction + softplus stream (x4 unrolled class lanes, MLP=4)
//  4: block reduce; global atomic; last block writes output and resets state
__global__ void __launch_bounds__(256) ACSL_fused_kernel(
    const float* __restrict__ logits, const float* __restrict__ labels,
    float* __restrict__ out) {
    __shared__ float s_v[8][TT];
    __shared__ short s_idx[8][TT];
    __shared__ short s_lab[TT];
    __shared__ short s_act[NC];           // compacted active classes
    __shared__ unsigned char s_wmf[NC];   // mask flag per class
    __shared__ int   s_nact;
    __shared__ float s_red[256];

    int i = blockIdx.x;
    int tid = threadIdx.x;
    const float* lbase = labels + (size_t)i * NC * TT;
    const float* base  = logits + (size_t)i * NC * TT;

    if (tid == 0) s_nact = 0;

    // ---- Phase 0: prefetch t=99 logit column; no dependency on phase 1 ----
    float lastcol = 0.0f;
    if (tid < NC) lastcol = __ldg(base + (size_t)tid * TT + (TT - 1));

    // ---- Phase 1: argmax over c, float4 along t, 4 independent max chains ----
    if (tid < 200) {
        int tg = tid % 25;           // t-group: covers t = 4*tg .. 4*tg+3
        int k  = tid / 25;           // c-chunk 0..7
        int c0 = (k == 0) ? 0 : (26 + 25 * (k - 1));
        int c1 = 26 + 25 * k;        // chunk0: [0,26), else 25 classes
        const float* p = lbase + tg * 4;
        float4 b = *reinterpret_cast<const float4*>(p + (size_t)c0 * TT);
        short i0 = (short)c0, i1 = (short)c0, i2 = (short)c0, i3 = (short)c0;
#pragma unroll 5
        for (int c = c0 + 1; c < c1; c++) {
            float4 v = *reinterpret_cast<const float4*>(p + (size_t)c * TT);
            if (v.x > b.x) { b.x = v.x; i0 = (short)c; }
            if (v.y > b.y) { b.y = v.y; i1 = (short)c; }
            if (v.z > b.z) { b.z = v.z; i2 = (short)c; }
            if (v.w > b.w) { b.w = v.w; i3 = (short)c; }
        }
        int t = tg * 4;
        s_v[k][t + 0] = b.x;  s_idx[k][t + 0] = i0;
        s_v[k][t + 1] = b.y;  s_idx[k][t + 1] = i1;
        s_v[k][t + 2] = b.z;  s_idx[k][t + 2] = i2;
        s_v[k][t + 3] = b.w;  s_idx[k][t + 3] = i3;
    }
    __syncthreads();
    if (tid < TT) {
        // reduce 8 chunks, ascending c order + strict '>' => first-max semantics
        float best = s_v[0][tid];
        short bi = s_idx[0][tid];
#pragma unroll
        for (int k = 1; k < 8; k++) {
            float v = s_v[k][tid];
            if (v > best) { best = v; bi = s_idx[k][tid]; }
        }
        s_lab[tid] = bi;
    }
    __syncthreads();

    // ---- Phase 2: weight mask for last snippet (flags + compaction) ----
    int lab99 = s_lab[TT - 1];
    bool isbg = (lab99 == NC - 1);
    if (tid < NC) {
        int c = tid;
        bool w;
        if (isbg) {
            // bg rows: FREQ_MASK [150,200) + BG_COL {200} + one-hot target at 200
            w = (c >= 150);
        } else {
            // non-bg: target one-hot OR sigmoid(logit_last) >= 0.3
            w = (c == lab99) || (lastcol >= THR);
        }
        s_wmf[c] = w ? 1 : 0;
        if (w) {
            int slot = atomicAdd(&s_nact, 1);
            s_act[slot] = (short)c;
        }
    }
    __syncthreads();

    float acc = 0.0f;

    // ---- Phase 3a: label-hit subtraction, hoisted out of the hot loop ----
    if (tid < TT) {
        int c = s_lab[tid];
        if (s_wmf[c]) acc -= __ldg(base + (size_t)c * TT + tid);
    }

    // ---- Phase 3b: softplus stream, 10 class-lanes x 25 t-groups, x4 unroll ----
    int nact = s_nact;
    if (tid < 250) {
        int q  = tid % 25;           // t-group
        int a0 = tid / 25;           // class lane 0..9
        const float* pq = base + q * 4;
        int a = a0;
        // 4 classes per iteration: 4 independent LDG.128 in flight (MLP=4)
        for (; a + 30 < nact; a += 40) {
            int c0 = s_act[a];
            int c1 = s_act[a + 10];
            int c2 = s_act[a + 20];
            int c3 = s_act[a + 30];
            float4 v0 = *reinterpret_cast<const float4*>(pq + (size_t)c0 * TT);
            float4 v1 = *reinterpret_cast<const float4*>(pq + (size_t)c1 * TT);
            float4 v2 = *reinterpret_cast<const float4*>(pq + (size_t)c2 * TT);
            float4 v3 = *reinterpret_cast<const float4*>(pq + (size_t)c3 * TT);
            acc += softplus4(v0);
            acc += softplus4(v1);
            acc += softplus4(v2);
            acc += softplus4(v3);
        }
        for (; a < nact; a += 10) {
            int c = s_act[a];
            float4 v = *reinterpret_cast<const float4*>(pq + (size_t)c * TT);
            acc += softplus4(v);
        }
    }

    // ---- block reduction ----
    s_red[tid] = acc;
    __syncthreads();
    for (int s = 128; s > 0; s >>= 1) {
        if (tid < s) s_red[tid] += s_red[tid + s];
        __syncthreads();
    }

    // ---- global accumulate; last block finalizes + resets for next replay ----
    if (tid == 0) {
        atomicAdd(&g_acc, (double)s_red[0]);
        __threadfence();
        unsigned int old = atomicAdd(&g_count, 1u);
        if (old == NI - 1) {
            double total = *(volatile double*)&g_acc;
            out[0] = (float)(total / (double)(NI * TT));
            g_acc = 0.0;
            __threadfence();
            g_count = 0;
        }
    }
}

extern "C" void kernel_launch(void* const* d_in, const int* in_sizes, int n_in,
                              void* d_out, int out_size) {
    const float* cls_logits = (const float*)d_in[0]; // [1024, 201, 100]
    const float* labels     = (const float*)d_in[1]; // [1024, 201, 100]
    float* out = (float*)d_out;

    ACSL_fused_kernel<<<NI, 256>>>(cls_logits, labels, out);
}